// round 9
// baseline (speedup 1.0000x reference)
#include <cuda_runtime.h>
#include <cuda_bf16.h>
#include <math.h>
#include <stdint.h>

#define HDIM 2048
#define NEXP 16
#define IDIM 768
#define TWO_I 1536
#define TMAX 2048
#define PMAX (TMAX*2)

typedef unsigned short ushort_t;

// ---------------- device scratch ----------------
__device__ int   g_count[NEXP];
__device__ int   g_segstart[NEXP + 1];
__device__ int   g_tok_e[TMAX * 2];
__device__ float g_tok_w[TMAX * 2];
__device__ int   g_pair_token[PMAX];
__device__ int   g_tok_pair[TMAX * 2];
__device__ __align__(16) float    g_gu[(size_t)PMAX * TWO_I];
__device__ __align__(16) ushort_t g_h_hi[(size_t)PMAX * IDIM];
__device__ __align__(16) ushort_t g_h_lo[(size_t)PMAX * IDIM];
__device__ __align__(16) float    g_y[(size_t)PMAX * HDIM];
__device__ float g_logits_fallback[TMAX * NEXP];

// ---------------- portable PTX helpers ----------------
__device__ __forceinline__ uint32_t smem_u32(const void* p) {
    uint32_t a;
    asm("{ .reg .u64 t; cvta.to.shared.u64 t, %1; cvt.u32.u64 %0, t; }" : "=r"(a) : "l"(p));
    return a;
}
#define LDMX4(r, addr) \
    asm volatile("ldmatrix.sync.aligned.m8n8.x4.shared.b16 {%0,%1,%2,%3}, [%4];" \
        : "=r"((r)[0]), "=r"((r)[1]), "=r"((r)[2]), "=r"((r)[3]) : "r"(addr))
#define MMA(acc, a, b0, b1) \
    asm volatile("mma.sync.aligned.m16n8k16.row.col.f32.bf16.bf16.f32 " \
        "{%0,%1,%2,%3}, {%4,%5,%6,%7}, {%8,%9}, {%0,%1,%2,%3};" \
        : "+f"((acc)[0]), "+f"((acc)[1]), "+f"((acc)[2]), "+f"((acc)[3]) \
        : "r"((a)[0]), "r"((a)[1]), "r"((a)[2]), "r"((a)[3]), "r"(b0), "r"(b1))
#define STSV2(addr, x, y) \
    asm volatile("st.shared.v2.b32 [%0], {%1,%2};" :: "r"((uint32_t)(addr)), "r"(x), "r"(y) : "memory")
#define STSV4(addr, x, y, z, w) \
    asm volatile("st.shared.v4.b32 [%0], {%1,%2,%3,%4};" :: "r"((uint32_t)(addr)), \
        "r"(x), "r"(y), "r"(z), "r"(w) : "memory")

// XOR swizzle: 64B row pitch = [hi 32B | lo 32B]; lo address = hi address ^ 32.
// IMPORTANT: never add byte offsets AFTER swizzling — always call swz(row, colbyte).
__device__ __forceinline__ uint32_t swz(uint32_t row, uint32_t colbyte) {
    return (row * 64 + colbyte) ^ ((row & 6) << 3);
}

__device__ __forceinline__ void split2(float x, float y, uint32_t& hi, uint32_t& lo) {
    uint32_t h;
    asm("cvt.rn.bf16x2.f32 %0, %1, %2;" : "=r"(h) : "f"(y), "f"(x));
    float hx = __uint_as_float(h << 16);
    float hy = __uint_as_float(h & 0xffff0000u);
    float lx = x - hx, ly = y - hy;
    uint32_t l;
    asm("cvt.rn.bf16x2.f32 %0, %1, %2;" : "=r"(l) : "f"(ly), "f"(lx));
    hi = h; lo = l;
}
__device__ __forceinline__ void split4(float4 v, uint32_t& h01, uint32_t& h23,
                                       uint32_t& l01, uint32_t& l23) {
    split2(v.x, v.y, h01, l01);
    split2(v.z, v.w, h23, l23);
}

// ---------------- small kernels ----------------
__global__ __launch_bounds__(128) void router_kernel(
    const float* __restrict__ x, const float* __restrict__ gw, float* __restrict__ logits, int T)
{
    int t = blockIdx.x, tid = threadIdx.x;
    float acc[NEXP];
#pragma unroll
    for (int e = 0; e < NEXP; e++) acc[e] = 0.f;
    const float* xr = x + (size_t)t * HDIM;
    for (int h = tid; h < HDIM; h += 128) {
        float xv = xr[h];
#pragma unroll
        for (int e = 0; e < NEXP; e++) acc[e] += xv * gw[e * HDIM + h];
    }
#pragma unroll
    for (int e = 0; e < NEXP; e++)
#pragma unroll
        for (int off = 16; off > 0; off >>= 1) acc[e] += __shfl_down_sync(0xffffffffu, acc[e], off);
    __shared__ float sred[4][NEXP];
    __shared__ float slog[NEXP];
    int warp = tid >> 5, lane = tid & 31;
    if (lane == 0)
#pragma unroll
        for (int e = 0; e < NEXP; e++) sred[warp][e] = acc[e];
    __syncthreads();
    if (tid < NEXP) {
        float v = sred[0][tid] + sred[1][tid] + sred[2][tid] + sred[3][tid];
        slog[tid] = v;
        logits[t * NEXP + tid] = v;
    }
    __syncthreads();
    if (tid == 0) {
        int i0 = 0; float v0 = slog[0];
#pragma unroll
        for (int e = 1; e < NEXP; e++) if (slog[e] > v0) { v0 = slog[e]; i0 = e; }
        int i1 = -1; float v1 = -INFINITY;
#pragma unroll
        for (int e = 0; e < NEXP; e++) { if (e == i0) continue; if (slog[e] > v1) { v1 = slog[e]; i1 = e; } }
        float e1 = expf(v1 - v0);
        float inv = 1.f / (1.f + e1);
        g_tok_e[t * 2 + 0] = i0; g_tok_w[t * 2 + 0] = inv;
        g_tok_e[t * 2 + 1] = i1; g_tok_w[t * 2 + 1] = e1 * inv;
        atomicAdd(&g_count[i0], 1);
        atomicAdd(&g_count[i1], 1);
    }
}

// offsets + dispatch merged, single block
__global__ __launch_bounds__(1024) void dispatch_kernel(int T)
{
    __shared__ int cur[NEXP];
    int tid = threadIdx.x;
    if (tid == 0) {
        int off = 0;
#pragma unroll
        for (int e = 0; e < NEXP; e++) { g_segstart[e] = off; cur[e] = off; off += g_count[e]; }
        g_segstart[NEXP] = off;
    }
    __syncthreads();
    for (int t = tid; t < T; t += 1024) {
#pragma unroll
        for (int s = 0; s < 2; s++) {
            int e = g_tok_e[t * 2 + s];
            int pos = atomicAdd(&cur[e], 1);
            g_pair_token[pos] = t;
            g_tok_pair[t * 2 + s] = pos;
        }
    }
}

// =============== GEMM geometry ===============
// CTA 64x128, 128 threads, 4 warps (2m x 2n), warp tile 32x64, BK=16, 2 CTAs/SM.
// Stage: A rows 0..63 at +0 (4KB), B rows 0..127 at +4096 (8KB); stage 12KB, 2 stages.
#define STAGE 12288
#define GSMEM 24576

// AKIND 0: A fp32 gathered (gu); AKIND 1: A pre-split bf16 (down)
template<int KDIM, int AKIND>
__global__ __launch_bounds__(128, 2) void gemm3(
    const float* __restrict__ Af32, const float* __restrict__ B,
    float* __restrict__ C, int ldc, size_t b_expert_stride)
{
    int e = blockIdx.z;
    int seg0 = g_segstart[e];
    int cnt  = g_segstart[e + 1] - seg0;
    int m0 = blockIdx.x * 64;
    if (m0 >= cnt) return;
    int n0 = blockIdx.y * 128;

    extern __shared__ char smem[];
    uint32_t sbase = smem_u32(smem);

    int tid = threadIdx.x;
    int lane = tid & 31, wid = tid >> 5;
    int warp_m = wid >> 1;     // 0..1
    int warp_n = wid & 1;      // 0..1

    // -------- loaders --------
    // A: 64 rows, 2 threads/row, 8 k-elems each
    int arow_l = tid >> 1;
    int ahalf  = tid & 1;
    int mrow = m0 + arow_l; if (mrow >= cnt) mrow = cnt - 1;
    const float* aptr = nullptr;
    const uint4 *ahip = nullptr, *alop = nullptr;
    if (AKIND == 0) {
        aptr = Af32 + (size_t)g_pair_token[seg0 + mrow] * KDIM + ahalf * 8;
    } else {
        ahip = (const uint4*)(g_h_hi + (size_t)(seg0 + mrow) * IDIM) + ahalf;
        alop = (const uint4*)(g_h_lo + (size_t)(seg0 + mrow) * IDIM) + ahalf;
    }
    uint32_t stsA = swz((uint32_t)arow_l, (uint32_t)(ahalf * 16));
    // B: 128 rows, 1 thread/row, 16 k-elems; hi bytes j*8 for pb[j] (swizzled individually!)
    const float* bptr = B + (size_t)e * b_expert_stride + (size_t)(n0 + tid) * KDIM;
    uint32_t stsB[4];
#pragma unroll
    for (int j = 0; j < 4; j++) stsB[j] = 4096 + swz((uint32_t)tid, (uint32_t)(j * 8));

    // -------- ldmatrix offsets --------
    int a_r = lane & 15, a_k = lane >> 4;
    int b_n = (lane & 7) + ((lane & 16) ? 8 : 0);
    int b_k = (lane & 8) ? 1 : 0;
    uint32_t a_hi[2], b_hi[4];
#pragma unroll
    for (int mf = 0; mf < 2; mf++)
        a_hi[mf] = swz((uint32_t)(warp_m * 32 + mf * 16 + a_r), (uint32_t)(a_k * 16));
#pragma unroll
    for (int nf = 0; nf < 4; nf++)
        b_hi[nf] = 4096 + swz((uint32_t)(warp_n * 64 + nf * 16 + b_n), (uint32_t)(b_k * 16));

    float acc[2][8][4];
#pragma unroll
    for (int mf = 0; mf < 2; mf++)
#pragma unroll
        for (int j = 0; j < 8; j++)
#pragma unroll
            for (int q = 0; q < 4; q++) acc[mf][j][q] = 0.f;

    const int NCH = KDIM / 16;
    float4 pa[2], pb[4];
    uint4  pah, pal;

    auto ldg_chunk = [&](int c) {
        const float4* bp = (const float4*)(bptr + c * 16);
#pragma unroll
        for (int j = 0; j < 4; j++) pb[j] = bp[j];
        if (AKIND == 0) {
            const float4* ap = (const float4*)(aptr + c * 16);
            pa[0] = ap[0]; pa[1] = ap[1];
        } else {
            pah = ahip[c * 2]; pal = alop[c * 2];
        }
    };
    auto sts_chunk = [&](uint32_t sb) {
        if (AKIND == 0) {
            uint32_t h01, h23, l01, l23, h45, h67, l45, l67;
            split4(pa[0], h01, h23, l01, l23);
            split4(pa[1], h45, h67, l45, l67);
            STSV4(sb + stsA,         h01, h23, h45, h67);
            STSV4(sb + (stsA ^ 32u), l01, l23, l45, l67);
        } else {
            STSV4(sb + stsA,         pah.x, pah.y, pah.z, pah.w);
            STSV4(sb + (stsA ^ 32u), pal.x, pal.y, pal.z, pal.w);
        }
#pragma unroll
        for (int j = 0; j < 4; j++) {
            uint32_t h01, h23, l01, l23;
            split4(pb[j], h01, h23, l01, l23);
            STSV2(sb + stsB[j],         h01, h23);
            STSV2(sb + (stsB[j] ^ 32u), l01, l23);
        }
    };

    ldg_chunk(0);
    sts_chunk(sbase);
    ldg_chunk(1);
    __syncthreads();

#pragma unroll 2
    for (int ch = 0; ch < NCH; ch++) {
        uint32_t sb  = sbase + (ch & 1) * STAGE;
        uint32_t sbn = sbase + ((ch + 1) & 1) * STAGE;
        if (ch + 1 < NCH) sts_chunk(sbn);
        uint32_t ahf[2][4], alf[2][4];
#pragma unroll
        for (int mf = 0; mf < 2; mf++) {
            LDMX4(ahf[mf], sb + a_hi[mf]);
            LDMX4(alf[mf], sb + (a_hi[mf] ^ 32u));
        }
#pragma unroll
        for (int nf = 0; nf < 4; nf++) {
            uint32_t bhf[4], blf[4];
            LDMX4(bhf, sb + b_hi[nf]);
            LDMX4(blf, sb + (b_hi[nf] ^ 32u));
#pragma unroll
            for (int mf = 0; mf < 2; mf++)
#pragma unroll
                for (int jj = 0; jj < 2; jj++) {
                    int j = nf * 2 + jj;
                    MMA(acc[mf][j], ahf[mf], bhf[jj * 2], bhf[jj * 2 + 1]);
                    MMA(acc[mf][j], alf[mf], bhf[jj * 2], bhf[jj * 2 + 1]);
                    MMA(acc[mf][j], ahf[mf], blf[jj * 2], blf[jj * 2 + 1]);
                }
        }
        if (ch + 2 < NCH) ldg_chunk(ch + 2);
        __syncthreads();
    }

    // -------- epilogue --------
    int erow = lane >> 2;
    int ecol = (lane & 3) * 2;
#pragma unroll
    for (int mf = 0; mf < 2; mf++) {
        int mloc0 = m0 + warp_m * 32 + mf * 16 + erow;
        int mloc1 = mloc0 + 8;
#pragma unroll
        for (int j = 0; j < 8; j++) {
            int nglob = n0 + warp_n * 64 + j * 8 + ecol;
            if (mloc0 < cnt)
                *(float2*)(C + (size_t)(seg0 + mloc0) * ldc + nglob) = make_float2(acc[mf][j][0], acc[mf][j][1]);
            if (mloc1 < cnt)
                *(float2*)(C + (size_t)(seg0 + mloc1) * ldc + nglob) = make_float2(acc[mf][j][2], acc[mf][j][3]);
        }
    }
}

// ---------------- SwiGLU elementwise: fp32 gu -> pre-split bf16 h ----------------
__global__ __launch_bounds__(256) void swiglu_kernel(int npairs)
{
    int idx = blockIdx.x * blockDim.x + threadIdx.x;
    if (idx >= npairs * (IDIM / 4)) return;
    int p = idx / (IDIM / 4);
    int c = idx % (IDIM / 4);
    float4 g4 = ((const float4*)g_gu)[(size_t)p * (TWO_I / 4) + c];
    float4 u4 = ((const float4*)g_gu)[(size_t)p * (TWO_I / 4) + (IDIM / 4) + c];
    float4 h;
    h.x = u4.x * g4.x / (1.f + expf(-g4.x));
    h.y = u4.y * g4.y / (1.f + expf(-g4.y));
    h.z = u4.z * g4.z / (1.f + expf(-g4.z));
    h.w = u4.w * g4.w / (1.f + expf(-g4.w));
    uint32_t h01, h23, l01, l23;
    split4(h, h01, h23, l01, l23);
    ((uint2*)g_h_hi)[idx] = make_uint2(h01, h23);
    ((uint2*)g_h_lo)[idx] = make_uint2(l01, l23);
}

// ---------------- combine ----------------
__global__ __launch_bounds__(256) void combine_kernel(float* __restrict__ out, int T)
{
    int idx = blockIdx.x * blockDim.x + threadIdx.x;
    if (idx >= T * (HDIM / 4)) return;
    int t = idx >> 9;
    int c = idx & 511;
    int p0 = g_tok_pair[2 * t], p1 = g_tok_pair[2 * t + 1];
    float w0 = g_tok_w[2 * t], w1 = g_tok_w[2 * t + 1];
    float4 a = ((const float4*)g_y)[(size_t)p0 * 512 + c];
    float4 b = ((const float4*)g_y)[(size_t)p1 * 512 + c];
    float4 o;
    o.x = w0 * a.x + w1 * b.x;
    o.y = w0 * a.y + w1 * b.y;
    o.z = w0 * a.z + w1 * b.z;
    o.w = w0 * a.w + w1 * b.w;
    ((float4*)out)[idx] = o;
}

// ---------------- launch ----------------
extern "C" void kernel_launch(void* const* d_in, const int* in_sizes, int n_in,
                              void* d_out, int out_size)
{
    const float* x   = (const float*)d_in[0];
    const float* gw  = (const float*)d_in[1];
    const float* gup = (const float*)d_in[2];
    const float* dw  = (const float*)d_in[3];
    float* out = (float*)d_out;

    int T = in_sizes[0] / HDIM;
    size_t main_sz = (size_t)T * HDIM;

    float* logits;
    if ((size_t)out_size >= main_sz + (size_t)T * NEXP) logits = out + main_sz;
    else cudaGetSymbolAddress((void**)&logits, g_logits_fallback);

    cudaFuncSetAttribute((const void*)gemm3<HDIM, 0>,
                         cudaFuncAttributeMaxDynamicSharedMemorySize, GSMEM);
    cudaFuncSetAttribute((const void*)gemm3<IDIM, 1>,
                         cudaFuncAttributeMaxDynamicSharedMemorySize, GSMEM);

    int* d_count; cudaGetSymbolAddress((void**)&d_count, g_count);
    cudaMemsetAsync(d_count, 0, NEXP * sizeof(int), 0);

    router_kernel<<<T, 128>>>(x, gw, logits, T);
    dispatch_kernel<<<1, 1024>>>(T);

    int mtiles = (T + 63) / 64;          // per-expert cnt <= T
    float* d_gu; cudaGetSymbolAddress((void**)&d_gu, g_gu);
    float* d_y;  cudaGetSymbolAddress((void**)&d_y,  g_y);

    dim3 gu_grid(mtiles, TWO_I / 128, NEXP);
    gemm3<HDIM, 0><<<gu_grid, 128, GSMEM>>>(x, gup, d_gu, TWO_I, (size_t)TWO_I * HDIM);

    int npairs = 2 * T;
    swiglu_kernel<<<(npairs * (IDIM / 4) + 255) / 256, 256>>>(npairs);

    dim3 dn_grid(mtiles, HDIM / 128, NEXP);
    gemm3<IDIM, 1><<<dn_grid, 128, GSMEM>>>(nullptr, dw, d_y, HDIM, (size_t)HDIM * IDIM);

    combine_kernel<<<(T * (HDIM / 4) + 255) / 256, 256>>>(out, T);
}

// round 10
// speedup vs baseline: 1.4556x; 1.4556x over previous
#include <cuda_runtime.h>
#include <cuda_bf16.h>
#include <math.h>
#include <stdint.h>

#define HDIM 2048
#define NEXP 16
#define IDIM 768
#define TWO_I 1536
#define TMAX 2048
#define PMAX (TMAX*2)

typedef unsigned short ushort_t;

// ---------------- device scratch ----------------
__device__ int   g_count[NEXP];
__device__ int   g_segstart[NEXP + 1];
__device__ int   g_tok_e[TMAX * 2];
__device__ float g_tok_w[TMAX * 2];
__device__ int   g_pair_token[PMAX];
__device__ float g_pair_w[PMAX];
__device__ __align__(16) float    g_gu[(size_t)PMAX * TWO_I];
__device__ __align__(16) ushort_t g_h_hi[(size_t)PMAX * IDIM];
__device__ __align__(16) ushort_t g_h_lo[(size_t)PMAX * IDIM];
__device__ float g_logits_fallback[TMAX * NEXP];

// ---------------- portable PTX helpers ----------------
__device__ __forceinline__ uint32_t smem_u32(const void* p) {
    uint32_t a;
    asm("{ .reg .u64 t; cvta.to.shared.u64 t, %1; cvt.u32.u64 %0, t; }" : "=r"(a) : "l"(p));
    return a;
}
#define LDMX4(r, addr) \
    asm volatile("ldmatrix.sync.aligned.m8n8.x4.shared.b16 {%0,%1,%2,%3}, [%4];" \
        : "=r"((r)[0]), "=r"((r)[1]), "=r"((r)[2]), "=r"((r)[3]) : "r"(addr))
#define MMA(acc, a, b0, b1) \
    asm volatile("mma.sync.aligned.m16n8k16.row.col.f32.bf16.bf16.f32 " \
        "{%0,%1,%2,%3}, {%4,%5,%6,%7}, {%8,%9}, {%0,%1,%2,%3};" \
        : "+f"((acc)[0]), "+f"((acc)[1]), "+f"((acc)[2]), "+f"((acc)[3]) \
        : "r"((a)[0]), "r"((a)[1]), "r"((a)[2]), "r"((a)[3]), "r"(b0), "r"(b1))
#define STSV2(addr, x, y) \
    asm volatile("st.shared.v2.b32 [%0], {%1,%2};" :: "r"((uint32_t)(addr)), "r"(x), "r"(y) : "memory")
#define STSV4(addr, x, y, z, w) \
    asm volatile("st.shared.v4.b32 [%0], {%1,%2,%3,%4};" :: "r"((uint32_t)(addr)), \
        "r"(x), "r"(y), "r"(z), "r"(w) : "memory")

// XOR swizzle for 64B-pitch rows (16B-granular; never add offsets after swizzling)
__device__ __forceinline__ uint32_t swz(uint32_t row, uint32_t colbyte) {
    return (row * 64 + colbyte) ^ ((row & 6) << 3);
}

// packed split: {x,y} fp32 -> bf16x2 hi + bf16x2 lo
__device__ __forceinline__ void split2(float x, float y, uint32_t& hi, uint32_t& lo) {
    uint32_t h;
    asm("cvt.rn.bf16x2.f32 %0, %1, %2;" : "=r"(h) : "f"(y), "f"(x));
    float hx = __uint_as_float(h << 16);
    float hy = __uint_as_float(h & 0xffff0000u);
    float lx = x - hx, ly = y - hy;
    uint32_t l;
    asm("cvt.rn.bf16x2.f32 %0, %1, %2;" : "=r"(l) : "f"(ly), "f"(lx));
    hi = h; lo = l;
}
__device__ __forceinline__ void split4(float4 v, uint32_t& h01, uint32_t& h23,
                                       uint32_t& l01, uint32_t& l23) {
    split2(v.x, v.y, h01, l01);
    split2(v.z, v.w, h23, l23);
}

// ---------------- small kernels ----------------
__global__ __launch_bounds__(128) void router_kernel(
    const float* __restrict__ x, const float* __restrict__ gw, float* __restrict__ logits, int T)
{
    int t = blockIdx.x, tid = threadIdx.x;
    float acc[NEXP];
#pragma unroll
    for (int e = 0; e < NEXP; e++) acc[e] = 0.f;
    const float* xr = x + (size_t)t * HDIM;
    for (int h = tid; h < HDIM; h += 128) {
        float xv = xr[h];
#pragma unroll
        for (int e = 0; e < NEXP; e++) acc[e] += xv * gw[e * HDIM + h];
    }
#pragma unroll
    for (int e = 0; e < NEXP; e++)
#pragma unroll
        for (int off = 16; off > 0; off >>= 1) acc[e] += __shfl_down_sync(0xffffffffu, acc[e], off);
    __shared__ float sred[4][NEXP];
    __shared__ float slog[NEXP];
    int warp = tid >> 5, lane = tid & 31;
    if (lane == 0)
#pragma unroll
        for (int e = 0; e < NEXP; e++) sred[warp][e] = acc[e];
    __syncthreads();
    if (tid < NEXP) {
        float v = sred[0][tid] + sred[1][tid] + sred[2][tid] + sred[3][tid];
        slog[tid] = v;
        logits[t * NEXP + tid] = v;
    }
    __syncthreads();
    if (tid == 0) {
        int i0 = 0; float v0 = slog[0];
#pragma unroll
        for (int e = 1; e < NEXP; e++) if (slog[e] > v0) { v0 = slog[e]; i0 = e; }
        int i1 = -1; float v1 = -INFINITY;
#pragma unroll
        for (int e = 0; e < NEXP; e++) { if (e == i0) continue; if (slog[e] > v1) { v1 = slog[e]; i1 = e; } }
        float e1 = expf(v1 - v0);
        float inv = 1.f / (1.f + e1);
        g_tok_e[t * 2 + 0] = i0; g_tok_w[t * 2 + 0] = inv;
        g_tok_e[t * 2 + 1] = i1; g_tok_w[t * 2 + 1] = e1 * inv;
        atomicAdd(&g_count[i0], 1);
        atomicAdd(&g_count[i1], 1);
    }
}

// offsets + dispatch merged, single block
__global__ __launch_bounds__(1024) void dispatch_kernel(int T)
{
    __shared__ int cur[NEXP];
    int tid = threadIdx.x;
    if (tid == 0) {
        int off = 0;
#pragma unroll
        for (int e = 0; e < NEXP; e++) { g_segstart[e] = off; cur[e] = off; off += g_count[e]; }
        g_segstart[NEXP] = off;
    }
    __syncthreads();
    for (int t = tid; t < T; t += 1024) {
#pragma unroll
        for (int s = 0; s < 2; s++) {
            int e = g_tok_e[t * 2 + s];
            int pos = atomicAdd(&cur[e], 1);
            g_pair_token[pos] = t;
            g_pair_w[pos]     = g_tok_w[t * 2 + s];
        }
    }
}

// ---------------- grouped GEMM (round-4 geometry: CTA 128x128, 8 warps 2m x 4n, BK=32) ----------------
// Stage layout: A_hi 0 | A_lo 8K | B_hi 16K | B_lo 24K, 2 stages = 64KB.
#define GSMEM 65536
#define STAGE 32768

// AKIND 0: A fp32 gathered (gu), C = g_gu;  AKIND 1: A pre-split bf16 (down), atomic scatter into out
template<int KDIM, int AKIND>
__global__ __launch_bounds__(256, 1) void gemm2(
    const float* __restrict__ Af32, const float* __restrict__ B,
    float* __restrict__ C, int ldc, size_t b_expert_stride)
{
    int e = blockIdx.z;
    int seg0 = g_segstart[e];
    int cnt  = g_segstart[e + 1] - seg0;
    int m0 = blockIdx.x * 128;
    if (m0 >= cnt) return;
    int n0 = blockIdx.y * 128;

    extern __shared__ char smem[];
    uint32_t sbase = smem_u32(smem);

    int tid = threadIdx.x;
    int lane = tid & 31, wid = tid >> 5;
    int warp_m = wid >> 2;
    int warp_n = wid & 3;

    // -------- loader setup --------
    int row  = tid >> 1;          // 0..127
    int half = tid & 1;
    int mrow = m0 + row; if (mrow >= cnt) mrow = cnt - 1;

    const float* aptr = nullptr;
    const uint4 *ahip = nullptr, *alop = nullptr;
    if (AKIND == 0) {
        aptr = Af32 + (size_t)g_pair_token[seg0 + mrow] * KDIM + half * 16;
    } else {
        ahip = (const uint4*)(g_h_hi + (size_t)(seg0 + mrow) * IDIM) + half * 2;
        alop = (const uint4*)(g_h_lo + (size_t)(seg0 + mrow) * IDIM) + half * 2;
    }
    const float* bptr = B + (size_t)e * b_expert_stride + (size_t)(n0 + row) * KDIM + half * 16;

    uint32_t sts8[4], sts16[2];
#pragma unroll
    for (int j = 0; j < 4; j++) sts8[j] = swz((uint32_t)row, (uint32_t)(half * 32 + j * 8));
#pragma unroll
    for (int j = 0; j < 2; j++) sts16[j] = swz((uint32_t)row, (uint32_t)(half * 32 + j * 16));

    // -------- ldmatrix offsets --------
    int a_r = lane & 15, a_k = lane >> 4;
    int b_n = (lane & 7) + ((lane & 16) ? 8 : 0);
    int b_k = (lane & 8) ? 1 : 0;
    uint32_t a_off[4][2], b_off[2][2];
#pragma unroll
    for (int mf = 0; mf < 4; mf++)
#pragma unroll
        for (int kk = 0; kk < 2; kk++)
            a_off[mf][kk] = swz((uint32_t)(warp_m * 64 + mf * 16 + a_r), (uint32_t)((kk * 2 + a_k) * 16));
#pragma unroll
    for (int nf = 0; nf < 2; nf++)
#pragma unroll
        for (int kk = 0; kk < 2; kk++)
            b_off[nf][kk] = swz((uint32_t)(warp_n * 32 + nf * 16 + b_n), (uint32_t)((kk * 2 + b_k) * 16));

    float acc[4][4][4];
#pragma unroll
    for (int mf = 0; mf < 4; mf++)
#pragma unroll
        for (int j = 0; j < 4; j++)
#pragma unroll
            for (int q = 0; q < 4; q++) acc[mf][j][q] = 0.f;

    const int NCH = KDIM / 32;
    float4 pa[4], pb[4];
    uint4  pah[2], pal[2];

    auto ldg_chunk = [&](int c) {
        const float* bp = bptr + c * 32;
#pragma unroll
        for (int j = 0; j < 4; j++) pb[j] = ((const float4*)bp)[j];
        if (AKIND == 0) {
            const float* ap = aptr + c * 32;
#pragma unroll
            for (int j = 0; j < 4; j++) pa[j] = ((const float4*)ap)[j];
        } else {
#pragma unroll
            for (int j = 0; j < 2; j++) { pah[j] = ahip[c * 4 + j]; pal[j] = alop[c * 4 + j]; }
        }
    };
    auto sts_chunk = [&](uint32_t sb) {
        if (AKIND == 0) {
#pragma unroll
            for (int j = 0; j < 4; j++) {
                uint32_t h01, h23, l01, l23;
                split4(pa[j], h01, h23, l01, l23);
                STSV2(sb + sts8[j],        h01, h23);
                STSV2(sb + 8192 + sts8[j], l01, l23);
            }
        } else {
#pragma unroll
            for (int j = 0; j < 2; j++) {
                STSV4(sb + sts16[j],        pah[j].x, pah[j].y, pah[j].z, pah[j].w);
                STSV4(sb + 8192 + sts16[j], pal[j].x, pal[j].y, pal[j].z, pal[j].w);
            }
        }
#pragma unroll
        for (int j = 0; j < 4; j++) {
            uint32_t h01, h23, l01, l23;
            split4(pb[j], h01, h23, l01, l23);
            STSV2(sb + 16384 + sts8[j], h01, h23);
            STSV2(sb + 24576 + sts8[j], l01, l23);
        }
    };

    ldg_chunk(0);
    sts_chunk(sbase);
    ldg_chunk(1);
    __syncthreads();

#pragma unroll 2
    for (int ch = 0; ch < NCH; ch++) {
        uint32_t sb  = sbase + (ch & 1) * STAGE;
        uint32_t sbn = sbase + ((ch + 1) & 1) * STAGE;
        if (ch + 1 < NCH) sts_chunk(sbn);
#pragma unroll
        for (int kk = 0; kk < 2; kk++) {
            uint32_t ahf[4][4], alf[4][4], bhf[2][4], blf[2][4];
#pragma unroll
            for (int mf = 0; mf < 4; mf++) {
                LDMX4(ahf[mf], sb + a_off[mf][kk]);
                LDMX4(alf[mf], sb + 8192 + a_off[mf][kk]);
            }
#pragma unroll
            for (int nf = 0; nf < 2; nf++) {
                LDMX4(bhf[nf], sb + 16384 + b_off[nf][kk]);
                LDMX4(blf[nf], sb + 24576 + b_off[nf][kk]);
            }
#pragma unroll
            for (int mf = 0; mf < 4; mf++)
#pragma unroll
                for (int j = 0; j < 4; j++) {
                    uint32_t b0h = bhf[j >> 1][(j & 1) * 2], b1h = bhf[j >> 1][(j & 1) * 2 + 1];
                    uint32_t b0l = blf[j >> 1][(j & 1) * 2], b1l = blf[j >> 1][(j & 1) * 2 + 1];
                    MMA(acc[mf][j], ahf[mf], b0h, b1h);
                    MMA(acc[mf][j], alf[mf], b0h, b1h);
                    MMA(acc[mf][j], ahf[mf], b0l, b1l);
                }
        }
        if (ch + 2 < NCH) ldg_chunk(ch + 2);
        __syncthreads();
    }

    // -------- epilogue --------
    int erow = lane >> 2;
    int ecol = (lane & 3) * 2;
    if (AKIND == 0) {
#pragma unroll
        for (int mf = 0; mf < 4; mf++) {
            int mloc0 = m0 + warp_m * 64 + mf * 16 + erow;
            int mloc1 = mloc0 + 8;
#pragma unroll
            for (int j = 0; j < 4; j++) {
                int nglob = n0 + warp_n * 32 + j * 8 + ecol;
                if (mloc0 < cnt)
                    *(float2*)(C + (size_t)(seg0 + mloc0) * ldc + nglob) = make_float2(acc[mf][j][0], acc[mf][j][1]);
                if (mloc1 < cnt)
                    *(float2*)(C + (size_t)(seg0 + mloc1) * ldc + nglob) = make_float2(acc[mf][j][2], acc[mf][j][3]);
            }
        }
    } else {
        // weighted atomic scatter into out[t, n] (exactly 2 adds/elem across all CTAs)
#pragma unroll
        for (int mf = 0; mf < 4; mf++) {
            int mloc0 = m0 + warp_m * 64 + mf * 16 + erow;
            int mloc1 = mloc0 + 8;
            int   t0 = 0, t1 = 0; float w0 = 0.f, w1 = 0.f;
            if (mloc0 < cnt) { t0 = g_pair_token[seg0 + mloc0]; w0 = g_pair_w[seg0 + mloc0]; }
            if (mloc1 < cnt) { t1 = g_pair_token[seg0 + mloc1]; w1 = g_pair_w[seg0 + mloc1]; }
#pragma unroll
            for (int j = 0; j < 4; j++) {
                int nglob = n0 + warp_n * 32 + j * 8 + ecol;
                if (mloc0 < cnt) {
                    atomicAdd(C + (size_t)t0 * HDIM + nglob,     w0 * acc[mf][j][0]);
                    atomicAdd(C + (size_t)t0 * HDIM + nglob + 1, w0 * acc[mf][j][1]);
                }
                if (mloc1 < cnt) {
                    atomicAdd(C + (size_t)t1 * HDIM + nglob,     w1 * acc[mf][j][2]);
                    atomicAdd(C + (size_t)t1 * HDIM + nglob + 1, w1 * acc[mf][j][3]);
                }
            }
        }
    }
}

// ---------------- SwiGLU elementwise: fp32 gu -> pre-split bf16 h ----------------
__global__ __launch_bounds__(256) void swiglu_kernel(int npairs)
{
    int idx = blockIdx.x * blockDim.x + threadIdx.x;
    if (idx >= npairs * (IDIM / 4)) return;
    int p = idx / (IDIM / 4);
    int c = idx % (IDIM / 4);
    float4 g4 = ((const float4*)g_gu)[(size_t)p * (TWO_I / 4) + c];
    float4 u4 = ((const float4*)g_gu)[(size_t)p * (TWO_I / 4) + (IDIM / 4) + c];
    float4 h;
    h.x = u4.x * g4.x / (1.f + expf(-g4.x));
    h.y = u4.y * g4.y / (1.f + expf(-g4.y));
    h.z = u4.z * g4.z / (1.f + expf(-g4.z));
    h.w = u4.w * g4.w / (1.f + expf(-g4.w));
    uint32_t h01, h23, l01, l23;
    split4(h, h01, h23, l01, l23);
    ((uint2*)g_h_hi)[idx] = make_uint2(h01, h23);
    ((uint2*)g_h_lo)[idx] = make_uint2(l01, l23);
}

// ---------------- launch ----------------
extern "C" void kernel_launch(void* const* d_in, const int* in_sizes, int n_in,
                              void* d_out, int out_size)
{
    const float* x   = (const float*)d_in[0];
    const float* gw  = (const float*)d_in[1];
    const float* gup = (const float*)d_in[2];
    const float* dw  = (const float*)d_in[3];
    float* out = (float*)d_out;

    int T = in_sizes[0] / HDIM;
    size_t main_sz = (size_t)T * HDIM;

    float* logits;
    if ((size_t)out_size >= main_sz + (size_t)T * NEXP) logits = out + main_sz;
    else cudaGetSymbolAddress((void**)&logits, g_logits_fallback);

    cudaFuncSetAttribute((const void*)gemm2<HDIM, 0>,
                         cudaFuncAttributeMaxDynamicSharedMemorySize, GSMEM);
    cudaFuncSetAttribute((const void*)gemm2<IDIM, 1>,
                         cudaFuncAttributeMaxDynamicSharedMemorySize, GSMEM);

    int* d_count; cudaGetSymbolAddress((void**)&d_count, g_count);
    cudaMemsetAsync(d_count, 0, NEXP * sizeof(int), 0);
    cudaMemsetAsync(out, 0, main_sz * sizeof(float), 0);   // down scatters into out

    router_kernel<<<T, 128>>>(x, gw, logits, T);
    dispatch_kernel<<<1, 1024>>>(T);

    int mtiles = (T + 127) / 128;
    float* d_gu; cudaGetSymbolAddress((void**)&d_gu, g_gu);

    dim3 gu_grid(mtiles, TWO_I / 128, NEXP);
    gemm2<HDIM, 0><<<gu_grid, 256, GSMEM>>>(x, gup, d_gu, TWO_I, (size_t)TWO_I * HDIM);

    int npairs = 2 * T;
    swiglu_kernel<<<(npairs * (IDIM / 4) + 255) / 256, 256>>>(npairs);

    dim3 dn_grid(mtiles, HDIM / 128, NEXP);
    gemm2<IDIM, 1><<<dn_grid, 256, GSMEM>>>(nullptr, dw, out, HDIM, (size_t)HDIM * IDIM);
}